// round 11
// baseline (speedup 1.0000x reference)
#include <cuda_runtime.h>

#define BATCH   4096
#define L_IN    16384
#define L_OUT   2044
#define TAPS    36          // composite kernel: 5 + 2*5 + 4*5 + 1
#define NOUT    4           // outputs per task
#define TASKS_PER_ROW (L_OUT / NOUT)     // 511
#define TPB     256
#define TILE_IN_Q 2056      // quads staged per tile (window needs 2055)
// pad: 1 quad per 8 quads -> padded quad index = q + (q>>3)
#define SMEM_Q  (TILE_IN_Q + (TILE_IN_Q >> 3) + 1)   // 2314 quads = 37,024 B per buffer
#define NBUF    3
#define GRID    1024
#define TPT     8           // tiles per block (GRID * TPT = 8192 tiles)
#define DYN_SMEM_BYTES (NBUF * SMEM_Q * 16)

__device__ __forceinline__ void issue_tile_load(float4* buf, const float4* x4, int t)
{
    const int row  = t >> 1;
    const int half = t & 1;
    const float4* src = x4 + (size_t)row * (L_IN / 4) + half * 2048;
    const int nQuad = half ? 2048 : TILE_IN_Q;     // tile1 tail is OOB -> zero-fill
    const int tid = threadIdx.x;
    #pragma unroll
    for (int it = 0; it < 9; it++) {
        int q = tid + it * TPB;
        if (q < TILE_IN_Q) {
            int srcBytes = (q < nQuad) ? 16 : 0;
            unsigned sdst = (unsigned)__cvta_generic_to_shared(&buf[q + (q >> 3)]);
            asm volatile("cp.async.cg.shared.global [%0], [%1], 16, %2;\n"
                         :: "r"(sdst), "l"(src + q), "r"(srcBytes));
        }
    }
    asm volatile("cp.async.commit_group;\n" ::: "memory");
}

__global__ __launch_bounds__(TPB) void encoder_fused_kernel(
    const float* __restrict__ x,
    const float* __restrict__ w1, const float* __restrict__ b1,
    const float* __restrict__ w2, const float* __restrict__ b2,
    const float* __restrict__ w3, const float* __restrict__ b3,
    float* __restrict__ out)
{
    extern __shared__ float4 xs[];            // NBUF buffers of SMEM_Q quads
    __shared__ float Wsh[TAPS];
    __shared__ float Csh;

    const int tid = threadIdx.x;

    // ---- composite weight + bias (tiny, per block) ----
    if (tid < TAPS) {
        float s = 0.0f;
        #pragma unroll
        for (int c = 0; c < 6; c++) {
            #pragma unroll
            for (int b = 0; b < 6; b++) {
                int a = tid - 4 * c - 2 * b;
                if (a >= 0 && a < 6)
                    s += w1[a] * w2[b] * w3[c];
            }
        }
        Wsh[tid] = s;
    }
    if (tid == 0) {
        float S2 = 0.0f, S3 = 0.0f;
        #pragma unroll
        for (int i = 0; i < 6; i++) { S2 += w2[i]; S3 += w3[i]; }
        Csh = b3[0] + b2[0] * S3 + b1[0] * S2 * S3;
    }

    const float4* x4 = reinterpret_cast<const float4*>(x);
    const int tbase = blockIdx.x * TPT;

    // prologue: prefetch tiles 0 and 1 (depth-2 pipeline)
    issue_tile_load(&xs[0], x4, tbase);
    issue_tile_load(&xs[SMEM_Q], x4, tbase + 1);

    int bufIdx = 0;
    #pragma unroll 1
    for (int i = 0; i < TPT; i++) {
        const int t = tbase + i;
        float4* cur = &xs[bufIdx * SMEM_Q];

        // wait for load of tile i: with one younger group possibly outstanding,
        // wait_group 1 suffices; last tile has nothing behind it -> wait_group 0.
        if (i < TPT - 1)
            asm volatile("cp.async.wait_group 1;\n" ::: "memory");
        else
            asm volatile("cp.async.wait_group 0;\n" ::: "memory");
        __syncthreads();   // cur loaded; all readers of the recycled buffer are done

        if (i + 2 < TPT) {
            int nb = bufIdx + 2; if (nb >= NBUF) nb -= NBUF;
            issue_tile_load(&xs[nb * SMEM_Q], x4, t + 2);   // overlaps compute below
        }

        // ---- compute: each thread = 4 consecutive outputs of tile t ----
        const int row  = t >> 1;
        const int half = t & 1;
        const int task = half * TPB + tid;     // 0..511 (511 invalid)
        if (task < TASKS_PER_ROW) {
            const float4* wq = &cur[9 * tid];  // window = 15 quads, pad skip at m>=8
            float f[60];
            #pragma unroll
            for (int m = 0; m < 15; m++) {
                float4 v = wq[m + (m >= 8 ? 1 : 0)];
                f[4 * m + 0] = v.x;
                f[4 * m + 1] = v.y;
                f[4 * m + 2] = v.z;
                f[4 * m + 3] = v.w;
            }

            const float C = Csh;
            float acc[NOUT];
            #pragma unroll
            for (int k = 0; k < NOUT; k++) {
                float a = C;
                #pragma unroll
                for (int tt = 0; tt < TAPS; tt++)
                    a = fmaf(Wsh[tt], f[8 * k + tt], a);
                acc[k] = a;
            }

            float4 o = make_float4(acc[0], acc[1], acc[2], acc[3]);
            float4* op = reinterpret_cast<float4*>(out + (size_t)row * L_OUT + task * NOUT);
            __stcs(op, o);
        }

        bufIdx = (bufIdx + 1 == NBUF) ? 0 : bufIdx + 1;
    }
}

extern "C" void kernel_launch(void* const* d_in, const int* in_sizes, int n_in,
                              void* d_out, int out_size)
{
    const float* x  = (const float*)d_in[0];
    const float* w1 = (const float*)d_in[1];
    const float* b1 = (const float*)d_in[2];
    const float* w2 = (const float*)d_in[3];
    const float* b2 = (const float*)d_in[4];
    const float* w3 = (const float*)d_in[5];
    const float* b3 = (const float*)d_in[6];
    float* out = (float*)d_out;

    static int configured = 0;
    if (!configured) {
        cudaFuncSetAttribute(encoder_fused_kernel,
                             cudaFuncAttributeMaxDynamicSharedMemorySize,
                             DYN_SMEM_BYTES);
        configured = 1;
    }

    encoder_fused_kernel<<<GRID, TPB, DYN_SMEM_BYTES>>>(x, w1, b1, w2, b2, w3, b3, out);
}

// round 12
// speedup vs baseline: 1.0423x; 1.0423x over previous
#include <cuda_runtime.h>

#define BATCH   4096
#define L_IN    16384
#define L_OUT   2044
#define TAPS    36          // composite kernel: 5 + 2*5 + 4*5 + 1
#define NOUT    4           // outputs per task
#define TPB     128
#define TILE_OUT 512        // outputs per tile (TPB * NOUT)
#define TILE_IN_Q 1032      // quads staged per tile (window needs 1031)
#define SMEM_Q  1032        // swizzled in place, no pad
#define NBUF    2
#define TILES_PER_ROW 4     // 4*512 covers 2044 (last tile 508 valid)
#define GRID    2048
#define TPT     8           // tiles per block (GRID*TPT = 16384 tiles)
#define DYN_SMEM_BYTES (NBUF * SMEM_Q * 16)

// XOR swizzle on quad index: rotates bank-group by (q>>3) within each 8-quad line
__device__ __forceinline__ int swz(int q) {
    return (q & ~7) | ((q ^ (q >> 3)) & 7);
}

__device__ __forceinline__ void issue_tile_load(float4* buf, const float4* x4, int t)
{
    const int row = t >> 2;
    const int c   = t & 3;                       // tile within row
    const float4* src = x4 + (size_t)row * (L_IN / 4) + c * 1024;
    const int nQuad = min(TILE_IN_Q, (L_IN / 4) - c * 1024);   // 1032, or 1024 on c==3
    const int tid = threadIdx.x;
    #pragma unroll
    for (int it = 0; it < 9; it++) {
        int q = tid + it * TPB;
        if (q < TILE_IN_Q) {
            int srcBytes = (q < nQuad) ? 16 : 0;   // OOB tail -> hardware zero-fill
            unsigned sdst = (unsigned)__cvta_generic_to_shared(&buf[swz(q)]);
            asm volatile("cp.async.cg.shared.global [%0], [%1], 16, %2;\n"
                         :: "r"(sdst), "l"(src + q), "r"(srcBytes));
        }
    }
    asm volatile("cp.async.commit_group;\n" ::: "memory");
}

__global__ __launch_bounds__(TPB) void encoder_fused_kernel(
    const float* __restrict__ x,
    const float* __restrict__ w1, const float* __restrict__ b1,
    const float* __restrict__ w2, const float* __restrict__ b2,
    const float* __restrict__ w3, const float* __restrict__ b3,
    float* __restrict__ out)
{
    extern __shared__ float4 xs[];            // NBUF buffers of SMEM_Q quads
    __shared__ float Wsh[TAPS];
    __shared__ float Csh;

    const int tid = threadIdx.x;

    // ---- composite weight + bias (tiny, per block) ----
    if (tid < TAPS) {
        float s = 0.0f;
        #pragma unroll
        for (int c = 0; c < 6; c++) {
            #pragma unroll
            for (int b = 0; b < 6; b++) {
                int a = tid - 4 * c - 2 * b;
                if (a >= 0 && a < 6)
                    s += w1[a] * w2[b] * w3[c];
            }
        }
        Wsh[tid] = s;
    }
    if (tid == 0) {
        float S2 = 0.0f, S3 = 0.0f;
        #pragma unroll
        for (int i = 0; i < 6; i++) { S2 += w2[i]; S3 += w3[i]; }
        Csh = b3[0] + b2[0] * S3 + b1[0] * S2 * S3;
    }

    const float4* x4 = reinterpret_cast<const float4*>(x);
    const int tbase = blockIdx.x * TPT;

    // prologue: prefetch first tile into buffer 0
    issue_tile_load(&xs[0], x4, tbase);

    #pragma unroll 1
    for (int i = 0; i < TPT; i++) {
        const int t = tbase + i;
        float4* cur = &xs[(i & 1) ? SMEM_Q : 0];
        float4* nxt = &xs[(i & 1) ? 0 : SMEM_Q];

        asm volatile("cp.async.wait_group 0;\n" ::: "memory");
        __syncthreads();   // cur loaded; everyone done reading nxt (prev compute)

        if (i + 1 < TPT)
            issue_tile_load(nxt, x4, t + 1);   // overlaps compute below

        // ---- compute: each thread = 4 consecutive outputs of tile t ----
        const int row = t >> 2;
        const int c   = t & 3;
        const int j0  = c * TILE_OUT + tid * NOUT;
        if (j0 + 3 < L_OUT) {
            // window floats [32*tid, 32*tid+60) = quads 8*tid .. 8*tid+14 (swizzled)
            const int wbase = 8 * tid;
            float f[60];
            #pragma unroll
            for (int m = 0; m < 15; m++) {
                float4 v = cur[swz(wbase + m)];
                f[4 * m + 0] = v.x;
                f[4 * m + 1] = v.y;
                f[4 * m + 2] = v.z;
                f[4 * m + 3] = v.w;
            }

            const float C = Csh;
            float acc[NOUT];
            #pragma unroll
            for (int k = 0; k < NOUT; k++) {
                float a = C;
                #pragma unroll
                for (int tt = 0; tt < TAPS; tt++)
                    a = fmaf(Wsh[tt], f[8 * k + tt], a);
                acc[k] = a;
            }

            float4 o = make_float4(acc[0], acc[1], acc[2], acc[3]);
            float4* op = reinterpret_cast<float4*>(out + (size_t)row * L_OUT + j0);
            __stcs(op, o);
        }
    }
}

extern "C" void kernel_launch(void* const* d_in, const int* in_sizes, int n_in,
                              void* d_out, int out_size)
{
    const float* x  = (const float*)d_in[0];
    const float* w1 = (const float*)d_in[1];
    const float* b1 = (const float*)d_in[2];
    const float* w2 = (const float*)d_in[3];
    const float* b2 = (const float*)d_in[4];
    const float* w3 = (const float*)d_in[5];
    const float* b3 = (const float*)d_in[6];
    float* out = (float*)d_out;

    static int configured = 0;
    if (!configured) {
        cudaFuncSetAttribute(encoder_fused_kernel,
                             cudaFuncAttributeMaxDynamicSharedMemorySize,
                             DYN_SMEM_BYTES);
        configured = 1;
    }

    encoder_fused_kernel<<<GRID, TPB, DYN_SMEM_BYTES>>>(x, w1, b1, w2, b2, w3, b3, out);
}